// round 9
// baseline (speedup 1.0000x reference)
#include <cuda_runtime.h>
#include <cstdint>

#define N_SITES 200000
#define C 128
#define NOFF 27
#define TOTAL (N_SITES * C)
#define TOTAL4 (TOTAL / 4)
#define TOTAL8 (TOTAL / 8)
#define TILE_M 128
#define NCHUNK ((N_SITES + TILE_M - 1) / TILE_M)   // 1563
#define STATS_ROWS 512
#define NB_STATS ((N_SITES + STATS_ROWS - 1) / STATS_ROWS)  // 391
#define EPS 1e-4f
#define W_ELEMS (NOFF * C * C)

// A smem stride (floats): 40 ≡ 8 (mod 32) -> conflict-free .64 frag loads
#define LDS_STRIDE 40
#define BUF_FLOATS (TILE_M * LDS_STRIDE)       // 5120 floats = 20 KB / stage
#define SMEM_DYN_BYTES (2 * BUF_FLOATS * 4)    // 40960

// ---------------- scratch (device globals; no allocations allowed) ----------
__device__ float g_buf1[TOTAL];
__device__ float g_buf2[TOTAL];
__device__ float g_wt1[W_ELEMS];   // [27][co][ci-permuted], tf32-rounded
__device__ float g_wt2[W_ELEMS];
__device__ float g_part[NB_STATS * C * 2];
__device__ float g_scale[C];
__device__ float g_bias[C];

// Column permutation within each 8-col group: stored order [c0,c4,c1,c5,c2,c6,c3,c7]
// -> thread tig reads its frag pair (c=tig, c=tig+4) as ONE 8-byte load.

// ---------------- helpers ----------------------------------------------------
__device__ __forceinline__ uint32_t smem_u32(const void* p) {
    uint32_t a;
    asm("{ .reg .u64 t; cvta.to.shared.u64 t, %1; cvt.u32.u64 %0, t; }" : "=r"(a) : "l"(p));
    return a;
}
__device__ __forceinline__ float rna_tf32(float x) {
    float r;
    asm("cvt.rna.tf32.f32 %0, %1;" : "=f"(r) : "f"(x));
    return r;
}
__device__ __forceinline__ void red_add2(float* p, float a, float b) {
    asm volatile("red.global.add.v2.f32 [%0], {%1, %2};"
                 :: "l"(p), "f"(a), "f"(b) : "memory");
}
__device__ __forceinline__ void st2(float* p, float a, float b) {
    asm volatile("st.global.v2.f32 [%0], {%1, %2};"
                 :: "l"(p), "f"(a), "f"(b) : "memory");
}
__device__ __forceinline__ void cp_async16(uint32_t dst, const void* src, int src_bytes) {
    asm volatile("cp.async.ca.shared.global [%0], [%1], 16, %2;"
                 :: "r"(dst), "l"(src), "r"(src_bytes) : "memory");
}
#define CP_COMMIT() asm volatile("cp.async.commit_group;" ::: "memory")
#define CP_WAIT(n)  asm volatile("cp.async.wait_group %0;" :: "n"(n) : "memory")

__device__ __forceinline__ void mma_tf32(float* d, const uint32_t* a, const uint32_t* b) {
    asm volatile(
        "mma.sync.aligned.m16n8k8.row.col.f32.tf32.tf32.f32 "
        "{%0,%1,%2,%3}, {%4,%5,%6,%7}, {%8,%9}, {%0,%1,%2,%3};"
        : "+f"(d[0]), "+f"(d[1]), "+f"(d[2]), "+f"(d[3])
        : "r"(a[0]), "r"(a[1]), "r"(a[2]), "r"(a[3]), "r"(b[0]), "r"(b[1]));
}

// ---- prep: W[k][ci][co] -> Wt[k][co][perm(ci)], rna-rounded -----------------
__global__ void __launch_bounds__(256) prep_w_kernel(const float* __restrict__ W,
                                                     float* __restrict__ Wt) {
    const int k = blockIdx.y;
    const int idx = blockIdx.x * 256 + threadIdx.x;  // over 16384 (write pos)
    const int co = idx >> 7;
    const int cp = idx & 127;                        // permuted ci position
    const int blk = cp >> 3, p = cp & 7;
    const int ci = (blk << 3) + ((p >> 1) + ((p & 1) << 2));  // inverse perm
    float v = __ldg(&W[(long)k * 16384 + ci * 128 + co]);
    Wt[(long)k * 16384 + co * 128 + cp] = rna_tf32(v);
}

// ---- one-shot rna rounding + column-pair permutation of features ------------
__global__ void __launch_bounds__(256) round_kernel(const float4* __restrict__ src,
                                                    float4* __restrict__ dst) {
    int i = blockIdx.x * 256 + threadIdx.x;   // over TOTAL8 (8 cols per thread)
    if (i >= TOTAL8) return;
    float4 v0 = __ldg(&src[2 * i]);
    float4 v1 = __ldg(&src[2 * i + 1]);
    v0.x = rna_tf32(v0.x); v0.y = rna_tf32(v0.y); v0.z = rna_tf32(v0.z); v0.w = rna_tf32(v0.w);
    v1.x = rna_tf32(v1.x); v1.y = rna_tf32(v1.y); v1.z = rna_tf32(v1.z); v1.w = rna_tf32(v1.w);
    dst[2 * i]     = make_float4(v0.x, v1.x, v0.y, v1.y);  // c0,c4,c1,c5
    dst[2 * i + 1] = make_float4(v0.z, v1.z, v0.w, v1.w);  // c2,c6,c3,c7
}

// ---- tf32 mma.sync pair-tile conv (A: cp.async smem; B: L1-hot LDG.64) ------
// Tile: 128 pairs x 128 outch x K=128, K chunked by 32, 2-stage pipeline.
// ATOMIC=false: center offset (k=13), plain stores (no zero pass needed).
// ATOMIC=true : 26 remaining offsets, red.global scatter-add.
template <bool ATOMIC>
__global__ void __launch_bounds__(256, 2) conv_mma_kernel(
    const float* __restrict__ feats, const float* __restrict__ Wt,
    const int* __restrict__ in_idx, const int* __restrict__ out_idx,
    float* __restrict__ out)
{
    extern __shared__ float dsm[];
    __shared__ int s_ii[TILE_M];
    __shared__ int s_oi[TILE_M];

    const int k = ATOMIC ? (blockIdx.y + (blockIdx.y >= 13 ? 1 : 0)) : 13;
    const long base = (long)blockIdx.x * TILE_M;
    const int* ik = in_idx + (long)k * N_SITES;
    if (ATOMIC && __ldg(&ik[base]) >= N_SITES) return;  // fully-padded chunk
    const int* ok = out_idx + (long)k * N_SITES;

    const int tid = threadIdx.x;
    const int wid = tid >> 5;
    const int lane = tid & 31;
    const int g = lane >> 2;       // group id (row within frag)
    const int tig = lane & 3;      // thread in group

    if (tid < TILE_M) {
        long p = base + tid;
        bool v = (p < N_SITES);
        s_ii[tid] = v ? __ldg(&ik[p]) : N_SITES;
        s_oi[tid] = v ? __ldg(&ok[p]) : N_SITES;
    }
    __syncthreads();

    const int warp_m = wid & 3;    // 0..3 -> 32-row band
    const int warp_n = wid >> 2;   // 0..1 -> 64-col band
    const int m0 = warp_m * 32;
    const int n0 = warp_n * 64;

    float acc[2][8][4];
    #pragma unroll
    for (int mf = 0; mf < 2; mf++)
        #pragma unroll
        for (int nf = 0; nf < 8; nf++)
            #pragma unroll
            for (int r = 0; r < 4; r++) acc[mf][nf][r] = 0.f;

    const float4* f4 = (const float4*)feats;
    const float2* w2 = (const float2*)(Wt + (long)k * 16384);  // row = 64 float2
    const int r_st = tid >> 3;          // staging row base
    const int g4 = tid & 7;             // float4 granule within 32-float row

    const uint32_t dsm_base = smem_u32(dsm);

    // ---- stage A chunk kc into pipeline buffer pb (0/1) via cp.async --------
    auto stage = [&](int kc, int pb) {
        const uint32_t a_u32 = dsm_base + pb * (BUF_FLOATS * 4);
        #pragma unroll
        for (int it = 0; it < 4; it++) {
            int r = r_st + it * 32;
            int ii = s_ii[r];
            bool v = (ii < N_SITES);
            const float4* src = f4 + (long)(v ? ii : 0) * 32 + kc * 8 + g4;
            cp_async16(a_u32 + r * (LDS_STRIDE * 4) + g4 * 16, src, v ? 16 : 0);
        }
    };

    // ---- compute chunk kc on pipeline buffer pb ------------------------------
    auto compute = [&](int kc, int pb) {
        const float2* Asb = (const float2*)(dsm + pb * BUF_FLOATS);  // row=20 f2
        #pragma unroll
        for (int ks = 0; ks < 4; ks++) {
            const int kb = kc * 16 + ks * 4 + tig;   // float2 col index in W row
            uint32_t b[8][2];
            #pragma unroll
            for (int nf = 0; nf < 8; nf++) {
                float2 bf = __ldg(&w2[(n0 + nf * 8 + g) * 64 + kb]);
                b[nf][0] = __float_as_uint(bf.x);
                b[nf][1] = __float_as_uint(bf.y);
            }
            const int ka = ks * 4 + tig;             // float2 col in A smem row
            #pragma unroll
            for (int mf = 0; mf < 2; mf++) {
                const int row = m0 + mf * 16 + g;
                float2 alo = Asb[row * 20 + ka];
                float2 ahi = Asb[(row + 8) * 20 + ka];
                uint32_t a[4];
                a[0] = __float_as_uint(alo.x);
                a[1] = __float_as_uint(ahi.x);
                a[2] = __float_as_uint(alo.y);
                a[3] = __float_as_uint(ahi.y);
                #pragma unroll
                for (int nf = 0; nf < 8; nf++)
                    mma_tf32(acc[mf][nf], a, b[nf]);
            }
        }
    };

    // ---- 2-stage software pipeline over 4 K-chunks ---------------------------
    stage(0, 0);
    CP_COMMIT();
    #pragma unroll
    for (int kc = 0; kc < 4; kc++) {
        if (kc < 3) {
            stage(kc + 1, (kc + 1) & 1);
            CP_COMMIT();
            CP_WAIT(1);
        } else {
            CP_WAIT(0);
        }
        __syncthreads();
        compute(kc, kc & 1);
        if (kc < 2) __syncthreads();  // before buf (kc&1) is restaged next iter
    }

    // ---- epilogue: rows -> out[oi] (original channel order) ------------------
    #pragma unroll
    for (int mf = 0; mf < 2; mf++) {
        const int r_lo = m0 + mf * 16 + g;
        const int oi_lo = s_oi[r_lo];
        const int oi_hi = s_oi[r_lo + 8];
        #pragma unroll
        for (int nf = 0; nf < 8; nf++) {
            const int col = n0 + nf * 8 + 2 * tig;
            if (oi_lo < N_SITES) {
                float* p = out + (long)oi_lo * C + col;
                if (ATOMIC) red_add2(p, acc[mf][nf][0], acc[mf][nf][1]);
                else        st2(p, acc[mf][nf][0], acc[mf][nf][1]);
            }
            if (oi_hi < N_SITES) {
                float* p = out + (long)oi_hi * C + col;
                if (ATOMIC) red_add2(p, acc[mf][nf][2], acc[mf][nf][3]);
                else        st2(p, acc[mf][nf][2], acc[mf][nf][3]);
            }
        }
    }
}

// ---------------- BN stats: per-block partial sum / sumsq per channel -------
__global__ void __launch_bounds__(256) bn_stats_kernel(const float* __restrict__ x) {
    const int b = blockIdx.x;
    const int r0 = b * STATS_ROWS;
    const int r1 = min(r0 + STATS_ROWS, N_SITES);
    const int c = threadIdx.x & 127;
    const int half = threadIdx.x >> 7;

    float s = 0.f, ss = 0.f;
    for (int r = r0 + half; r < r1; r += 2) {
        float v = __ldg(&x[(long)r * C + c]);
        s += v;
        ss += v * v;
    }
    __shared__ float sm[512];
    sm[threadIdx.x] = s;
    sm[256 + threadIdx.x] = ss;
    __syncthreads();
    if (half == 0) {
        g_part[((long)b * C + c) * 2 + 0] = s + sm[threadIdx.x + 128];
        g_part[((long)b * C + c) * 2 + 1] = ss + sm[256 + threadIdx.x + 128];
    }
}

// fixed-order finalize (4 workers per channel): deterministic mean/var
__global__ void __launch_bounds__(512) bn_final_kernel(const float* __restrict__ gamma,
                                                       const float* __restrict__ beta) {
    const int c = threadIdx.x & 127;
    const int w = threadIdx.x >> 7;  // 0..3
    float s = 0.f, ss = 0.f;
    for (int b = w; b < NB_STATS; b += 4) {
        s  += g_part[((long)b * C + c) * 2 + 0];
        ss += g_part[((long)b * C + c) * 2 + 1];
    }
    __shared__ float sm[1024];
    sm[threadIdx.x] = s;
    sm[512 + threadIdx.x] = ss;
    __syncthreads();
    if (w == 0) {
        #pragma unroll
        for (int j = 1; j < 4; j++) {
            s  += sm[j * 128 + c];
            ss += sm[512 + j * 128 + c];
        }
        const float inv_n = 1.f / (float)N_SITES;
        float m = s * inv_n;
        float v = ss * inv_n - m * m;
        float sc = gamma[c] * rsqrtf(v + EPS);
        g_scale[c] = sc;
        g_bias[c] = beta[c] - m * sc;
    }
}

// ---- elementwise: in-place BN + ReLU + rna + pair-permute (conv2 input) -----
__global__ void __launch_bounds__(256) bn_relu_kernel(float* __restrict__ x) {
    int i = blockIdx.x * 256 + threadIdx.x;   // over TOTAL8
    if (i >= TOTAL8) return;
    float4* x4 = (float4*)x;
    float4 v0 = x4[2 * i];
    float4 v1 = x4[2 * i + 1];
    int j = (2 * i) & 31;                     // float4 granule index within row
    float4 s0 = ((const float4*)g_scale)[j];
    float4 b0 = ((const float4*)g_bias)[j];
    float4 s1 = ((const float4*)g_scale)[j + 1];
    float4 b1 = ((const float4*)g_bias)[j + 1];
    v0.x = rna_tf32(fmaxf(fmaf(v0.x, s0.x, b0.x), 0.f));
    v0.y = rna_tf32(fmaxf(fmaf(v0.y, s0.y, b0.y), 0.f));
    v0.z = rna_tf32(fmaxf(fmaf(v0.z, s0.z, b0.z), 0.f));
    v0.w = rna_tf32(fmaxf(fmaf(v0.w, s0.w, b0.w), 0.f));
    v1.x = rna_tf32(fmaxf(fmaf(v1.x, s1.x, b1.x), 0.f));
    v1.y = rna_tf32(fmaxf(fmaf(v1.y, s1.y, b1.y), 0.f));
    v1.z = rna_tf32(fmaxf(fmaf(v1.z, s1.z, b1.z), 0.f));
    v1.w = rna_tf32(fmaxf(fmaf(v1.w, s1.w, b1.w), 0.f));
    x4[2 * i]     = make_float4(v0.x, v1.x, v0.y, v1.y);
    x4[2 * i + 1] = make_float4(v0.z, v1.z, v0.w, v1.w);
}

// ---------------- elementwise: BN + residual + ReLU -> output ---------------
__global__ void __launch_bounds__(256) apply_res_kernel(
    const float* __restrict__ x, const float* __restrict__ feats,
    float* __restrict__ out)
{
    int i = blockIdx.x * 256 + threadIdx.x;
    if (i >= TOTAL4) return;
    float4 v = ((const float4*)x)[i];
    float4 f = ((const float4*)feats)[i];
    int c4 = i & 31;
    float4 s = ((const float4*)g_scale)[c4];
    float4 b = ((const float4*)g_bias)[c4];
    float4 o;
    o.x = fmaxf(fmaf(v.x, s.x, b.x) + f.x, 0.f);
    o.y = fmaxf(fmaf(v.y, s.y, b.y) + f.y, 0.f);
    o.z = fmaxf(fmaf(v.z, s.z, b.z) + f.z, 0.f);
    o.w = fmaxf(fmaf(v.w, s.w, b.w) + f.w, 0.f);
    ((float4*)out)[i] = o;
}

// ---------------- launch ----------------------------------------------------
extern "C" void kernel_launch(void* const* d_in, const int* in_sizes, int n_in,
                              void* d_out, int out_size) {
    const float* feats  = (const float*)d_in[0];
    const float* W1     = (const float*)d_in[1];
    const float* gamma1 = (const float*)d_in[2];
    const float* beta1  = (const float*)d_in[3];
    const float* W2     = (const float*)d_in[4];
    const float* gamma2 = (const float*)d_in[5];
    const float* beta2  = (const float*)d_in[6];
    const int*   iidx   = (const int*)d_in[7];
    const int*   oidx   = (const int*)d_in[8];
    float* out = (float*)d_out;

    void *pb1, *pb2, *pw1, *pw2;
    cudaGetSymbolAddress(&pb1, g_buf1);
    cudaGetSymbolAddress(&pb2, g_buf2);
    cudaGetSymbolAddress(&pw1, g_wt1);
    cudaGetSymbolAddress(&pw2, g_wt2);
    float* buf1 = (float*)pb1;
    float* buf2 = (float*)pb2;
    float* wt1  = (float*)pw1;
    float* wt2  = (float*)pw2;

    cudaFuncSetAttribute(conv_mma_kernel<false>,
                         cudaFuncAttributeMaxDynamicSharedMemorySize, SMEM_DYN_BYTES);
    cudaFuncSetAttribute(conv_mma_kernel<true>,
                         cudaFuncAttributeMaxDynamicSharedMemorySize, SMEM_DYN_BYTES);

    const int EB4 = (TOTAL4 + 255) / 256;
    const int EB8 = (TOTAL8 + 255) / 256;
    dim3 cgc(NCHUNK, 1);    // center store pass
    dim3 cga(NCHUNK, 26);   // atomic pass (26 non-center offsets)
    dim3 pg(64, NOFF);

    // weight permute/round; rounded+permuted copy of features into buf2
    prep_w_kernel<<<pg, 256>>>(W1, wt1);
    prep_w_kernel<<<pg, 256>>>(W2, wt2);
    round_kernel<<<EB8, 256>>>((const float4*)feats, (float4*)buf2);

    // conv1 (center store, then 26-offset scatter) -> BN1 -> ReLU(+rna+perm)
    conv_mma_kernel<false><<<cgc, 256, SMEM_DYN_BYTES>>>(buf2, wt1, iidx, oidx, buf1);
    conv_mma_kernel<true ><<<cga, 256, SMEM_DYN_BYTES>>>(buf2, wt1, iidx, oidx, buf1);
    bn_stats_kernel<<<NB_STATS, 256>>>(buf1);
    bn_final_kernel<<<1, 512>>>(gamma1, beta1);
    bn_relu_kernel<<<EB8, 256>>>(buf1);

    // conv2 -> BN2 -> +residual -> ReLU
    conv_mma_kernel<false><<<cgc, 256, SMEM_DYN_BYTES>>>(buf1, wt2, iidx, oidx, buf2);
    conv_mma_kernel<true ><<<cga, 256, SMEM_DYN_BYTES>>>(buf1, wt2, iidx, oidx, buf2);
    bn_stats_kernel<<<NB_STATS, 256>>>(buf2);
    bn_final_kernel<<<1, 512>>>(gamma2, beta2);
    apply_res_kernel<<<EB4, 256>>>(buf2, feats, out);
}

// round 12
// speedup vs baseline: 1.2987x; 1.2987x over previous
#include <cuda_runtime.h>
#include <cstdint>

#define N_SITES 200000
#define C 128
#define NOFF 27
#define TOTAL (N_SITES * C)
#define TOTAL4 (TOTAL / 4)
#define TOTAL8 (TOTAL / 8)
#define TILE_M 128
#define NCHUNK ((N_SITES + TILE_M - 1) / TILE_M)   // 1563
#define STATS_ROWS 512
#define NB_STATS ((N_SITES + STATS_ROWS - 1) / STATS_ROWS)  // 391
#define EPS 1e-4f
#define W_ELEMS (NOFF * C * C)

// smem row stride (floats): 40 ≡ 8 (mod 32) -> conflict-free .64 frag loads
#define LDS_STRIDE 40
#define TILE_FLOATS (TILE_M * LDS_STRIDE)        // 5120 floats = 20 KB per operand
#define STAGE_FLOATS (2 * TILE_FLOATS)           // A + B = 10240 floats = 40 KB
#define SMEM_DYN_BYTES (2 * STAGE_FLOATS * 4)    // 81920 (2 pipeline stages)

// ---------------- scratch (device globals; no allocations allowed) ----------
__device__ float g_buf1[TOTAL];
__device__ float g_buf2[TOTAL];
__device__ float g_wt1[W_ELEMS];   // [27][co][perm(ci)], tf32-rounded
__device__ float g_wt2[W_ELEMS];
__device__ float g_part[NB_STATS * C * 2];
__device__ float g_scale[C];
__device__ float g_bias[C];

// Column permutation within each 8-col group: stored order [c0,c4,c1,c5,c2,c6,c3,c7]
// -> thread tig reads its frag pair (c=tig, c=tig+4) as ONE 8-byte LDS.

// ---------------- helpers ----------------------------------------------------
__device__ __forceinline__ uint32_t smem_u32(const void* p) {
    uint32_t a;
    asm("{ .reg .u64 t; cvta.to.shared.u64 t, %1; cvt.u32.u64 %0, t; }" : "=r"(a) : "l"(p));
    return a;
}
__device__ __forceinline__ float rna_tf32(float x) {
    float r;
    asm("cvt.rna.tf32.f32 %0, %1;" : "=f"(r) : "f"(x));
    return r;
}
__device__ __forceinline__ void red_add2(float* p, float a, float b) {
    asm volatile("red.global.add.v2.f32 [%0], {%1, %2};"
                 :: "l"(p), "f"(a), "f"(b) : "memory");
}
__device__ __forceinline__ void st2(float* p, float a, float b) {
    asm volatile("st.global.v2.f32 [%0], {%1, %2};"
                 :: "l"(p), "f"(a), "f"(b) : "memory");
}
__device__ __forceinline__ void cp_async16(uint32_t dst, const void* src, int src_bytes) {
    asm volatile("cp.async.ca.shared.global [%0], [%1], 16, %2;"
                 :: "r"(dst), "l"(src), "r"(src_bytes) : "memory");
}
#define CP_COMMIT() asm volatile("cp.async.commit_group;" ::: "memory")
#define CP_WAIT(n)  asm volatile("cp.async.wait_group %0;" :: "n"(n) : "memory")

__device__ __forceinline__ void mma_tf32(float* d, const uint32_t* a, const uint32_t* b) {
    asm volatile(
        "mma.sync.aligned.m16n8k8.row.col.f32.tf32.tf32.f32 "
        "{%0,%1,%2,%3}, {%4,%5,%6,%7}, {%8,%9}, {%0,%1,%2,%3};"
        : "+f"(d[0]), "+f"(d[1]), "+f"(d[2]), "+f"(d[3])
        : "r"(a[0]), "r"(a[1]), "r"(a[2]), "r"(a[3]), "r"(b[0]), "r"(b[1]));
}

// ---- prep: W[k][ci][co] -> Wt[k][co][perm(ci)], rna-rounded -----------------
__global__ void __launch_bounds__(256) prep_w_kernel(const float* __restrict__ W,
                                                     float* __restrict__ Wt) {
    const int k = blockIdx.y;
    const int idx = blockIdx.x * 256 + threadIdx.x;  // over 16384 (write pos)
    const int co = idx >> 7;
    const int cp = idx & 127;                        // permuted ci position
    const int blk = cp >> 3, p = cp & 7;
    const int ci = (blk << 3) + ((p >> 1) + ((p & 1) << 2));  // inverse perm
    float v = __ldg(&W[(long)k * 16384 + ci * 128 + co]);
    Wt[(long)k * 16384 + co * 128 + cp] = rna_tf32(v);
}

// ---- one-shot rna rounding + column-pair permutation of features ------------
__global__ void __launch_bounds__(256) round_kernel(const float4* __restrict__ src,
                                                    float4* __restrict__ dst) {
    int i = blockIdx.x * 256 + threadIdx.x;   // over TOTAL8 (8 cols per thread)
    if (i >= TOTAL8) return;
    float4 v0 = __ldg(&src[2 * i]);
    float4 v1 = __ldg(&src[2 * i + 1]);
    v0.x = rna_tf32(v0.x); v0.y = rna_tf32(v0.y); v0.z = rna_tf32(v0.z); v0.w = rna_tf32(v0.w);
    v1.x = rna_tf32(v1.x); v1.y = rna_tf32(v1.y); v1.z = rna_tf32(v1.z); v1.w = rna_tf32(v1.w);
    dst[2 * i]     = make_float4(v0.x, v1.x, v0.y, v1.y);  // c0,c4,c1,c5
    dst[2 * i + 1] = make_float4(v0.z, v1.z, v0.w, v1.w);  // c2,c6,c3,c7
}

// ---- tf32 mma.sync pair-tile conv (A+B cp.async staged, .64 frag loads) -----
// Tile: 128 pairs x 128 outch x K=128, K chunked by 32, 2-stage pipeline.
// ATOMIC=false: center offset (k=13), plain stores (no zero pass needed).
// ATOMIC=true : 26 remaining offsets, red.global scatter-add.
template <bool ATOMIC>
__global__ void __launch_bounds__(256, 2) conv_mma_kernel(
    const float* __restrict__ feats, const float* __restrict__ Wt,
    const int* __restrict__ in_idx, const int* __restrict__ out_idx,
    float* __restrict__ out)
{
    extern __shared__ float dsm[];
    __shared__ int s_ii[TILE_M];
    __shared__ int s_oi[TILE_M];

    const int k = ATOMIC ? (blockIdx.y + (blockIdx.y >= 13 ? 1 : 0)) : 13;
    const long base = (long)blockIdx.x * TILE_M;
    const int* ik = in_idx + (long)k * N_SITES;
    if (ATOMIC && __ldg(&ik[base]) >= N_SITES) return;  // fully-padded chunk
    const int* ok = out_idx + (long)k * N_SITES;

    const int tid = threadIdx.x;
    const int wid = tid >> 5;
    const int lane = tid & 31;
    const int g = lane >> 2;       // group id (row within frag)
    const int tig = lane & 3;      // thread in group

    if (tid < TILE_M) {
        long p = base + tid;
        bool v = (p < N_SITES);
        s_ii[tid] = v ? __ldg(&ik[p]) : N_SITES;
        s_oi[tid] = v ? __ldg(&ok[p]) : N_SITES;
    }
    __syncthreads();

    const int warp_m = wid & 3;    // 0..3 -> 32-row band
    const int warp_n = wid >> 2;   // 0..1 -> 64-col band
    const int m0 = warp_m * 32;
    const int n0 = warp_n * 64;

    float acc[2][8][4];
    #pragma unroll
    for (int mf = 0; mf < 2; mf++)
        #pragma unroll
        for (int nf = 0; nf < 8; nf++)
            #pragma unroll
            for (int r = 0; r < 4; r++) acc[mf][nf][r] = 0.f;

    const float4* f4 = (const float4*)feats;
    const float4* w4 = (const float4*)(Wt + (long)k * 16384);
    const int r_st = tid >> 3;          // staging row base
    const int g4 = tid & 7;             // float4 granule within 32-float row

    const uint32_t dsm_base = smem_u32(dsm);

    // ---- stage A+B chunk kc into pipeline buffer pb (0/1) via cp.async ------
    auto stage = [&](int kc, int pb) {
        const uint32_t a_u32 = dsm_base + pb * (STAGE_FLOATS * 4);
        const uint32_t b_u32 = a_u32 + TILE_FLOATS * 4;
        #pragma unroll
        for (int it = 0; it < 4; it++) {
            int r = r_st + it * 32;
            int ii = s_ii[r];
            bool v = (ii < N_SITES);
            const float4* src = f4 + (long)(v ? ii : 0) * 32 + kc * 8 + g4;
            cp_async16(a_u32 + r * (LDS_STRIDE * 4) + g4 * 16, src, v ? 16 : 0);
        }
        #pragma unroll
        for (int it = 0; it < 4; it++) {
            int r = r_st + it * 32;
            cp_async16(b_u32 + r * (LDS_STRIDE * 4) + g4 * 16,
                       w4 + r * 32 + kc * 8 + g4, 16);
        }
    };

    // ---- compute on pipeline buffer pb (all frag loads are LDS.64) ----------
    auto compute = [&](int pb) {
        const float2* Asb = (const float2*)(dsm + pb * STAGE_FLOATS);  // row=20 f2
        const float2* Bsb = Asb + TILE_M * 20;
        #pragma unroll
        for (int ks = 0; ks < 4; ks++) {
            const int ka = ks * 4 + tig;             // float2 col within row
            uint32_t b[8][2];
            #pragma unroll
            for (int nf = 0; nf < 8; nf++) {
                float2 bf = Bsb[(n0 + nf * 8 + g) * 20 + ka];
                b[nf][0] = __float_as_uint(bf.x);    // orig col tig
                b[nf][1] = __float_as_uint(bf.y);    // orig col tig+4
            }
            #pragma unroll
            for (int mf = 0; mf < 2; mf++) {
                const int row = m0 + mf * 16 + g;
                float2 alo = Asb[row * 20 + ka];
                float2 ahi = Asb[(row + 8) * 20 + ka];
                uint32_t a[4];
                a[0] = __float_as_uint(alo.x);
                a[1] = __float_as_uint(ahi.x);
                a[2] = __float_as_uint(alo.y);
                a[3] = __float_as_uint(ahi.y);
                #pragma unroll
                for (int nf = 0; nf < 8; nf++)
                    mma_tf32(acc[mf][nf], a, b[nf]);
            }
        }
    };

    // ---- 2-stage software pipeline over 4 K-chunks ---------------------------
    stage(0, 0);
    CP_COMMIT();
    #pragma unroll
    for (int kc = 0; kc < 4; kc++) {
        if (kc < 3) {
            stage(kc + 1, (kc + 1) & 1);
            CP_COMMIT();
            CP_WAIT(1);
        } else {
            CP_WAIT(0);
        }
        __syncthreads();
        compute(kc & 1);
        if (kc < 2) __syncthreads();  // before buf (kc&1) is restaged next iter
    }

    // ---- epilogue: rows -> out[oi] (original channel order) ------------------
    #pragma unroll
    for (int mf = 0; mf < 2; mf++) {
        const int r_lo = m0 + mf * 16 + g;
        const int oi_lo = s_oi[r_lo];
        const int oi_hi = s_oi[r_lo + 8];
        #pragma unroll
        for (int nf = 0; nf < 8; nf++) {
            const int col = n0 + nf * 8 + 2 * tig;
            if (oi_lo < N_SITES) {
                float* p = out + (long)oi_lo * C + col;
                if (ATOMIC) red_add2(p, acc[mf][nf][0], acc[mf][nf][1]);
                else        st2(p, acc[mf][nf][0], acc[mf][nf][1]);
            }
            if (oi_hi < N_SITES) {
                float* p = out + (long)oi_hi * C + col;
                if (ATOMIC) red_add2(p, acc[mf][nf][2], acc[mf][nf][3]);
                else        st2(p, acc[mf][nf][2], acc[mf][nf][3]);
            }
        }
    }
}

// ---------------- BN stats: per-block partial sum / sumsq per channel -------
__global__ void __launch_bounds__(256) bn_stats_kernel(const float* __restrict__ x) {
    const int b = blockIdx.x;
    const int r0 = b * STATS_ROWS;
    const int r1 = min(r0 + STATS_ROWS, N_SITES);
    const int c = threadIdx.x & 127;
    const int half = threadIdx.x >> 7;

    float s = 0.f, ss = 0.f;
    for (int r = r0 + half; r < r1; r += 2) {
        float v = __ldg(&x[(long)r * C + c]);
        s += v;
        ss += v * v;
    }
    __shared__ float sm[512];
    sm[threadIdx.x] = s;
    sm[256 + threadIdx.x] = ss;
    __syncthreads();
    if (half == 0) {
        g_part[((long)b * C + c) * 2 + 0] = s + sm[threadIdx.x + 128];
        g_part[((long)b * C + c) * 2 + 1] = ss + sm[256 + threadIdx.x + 128];
    }
}

// fixed-order finalize (4 workers per channel): deterministic mean/var
__global__ void __launch_bounds__(512) bn_final_kernel(const float* __restrict__ gamma,
                                                       const float* __restrict__ beta) {
    const int c = threadIdx.x & 127;
    const int w = threadIdx.x >> 7;  // 0..3
    float s = 0.f, ss = 0.f;
    for (int b = w; b < NB_STATS; b += 4) {
        s  += g_part[((long)b * C + c) * 2 + 0];
        ss += g_part[((long)b * C + c) * 2 + 1];
    }
    __shared__ float sm[1024];
    sm[threadIdx.x] = s;
    sm[512 + threadIdx.x] = ss;
    __syncthreads();
    if (w == 0) {
        #pragma unroll
        for (int j = 1; j < 4; j++) {
            s  += sm[j * 128 + c];
            ss += sm[512 + j * 128 + c];
        }
        const float inv_n = 1.f / (float)N_SITES;
        float m = s * inv_n;
        float v = ss * inv_n - m * m;
        float sc = gamma[c] * rsqrtf(v + EPS);
        g_scale[c] = sc;
        g_bias[c] = beta[c] - m * sc;
    }
}

// ---- elementwise: in-place BN + ReLU + rna + pair-permute (conv2 input) -----
__global__ void __launch_bounds__(256) bn_relu_kernel(float* __restrict__ x) {
    int i = blockIdx.x * 256 + threadIdx.x;   // over TOTAL8
    if (i >= TOTAL8) return;
    float4* x4 = (float4*)x;
    float4 v0 = x4[2 * i];
    float4 v1 = x4[2 * i + 1];
    int j = (2 * i) & 31;                     // float4 granule index within row
    float4 s0 = ((const float4*)g_scale)[j];
    float4 b0 = ((const float4*)g_bias)[j];
    float4 s1 = ((const float4*)g_scale)[j + 1];
    float4 b1 = ((const float4*)g_bias)[j + 1];
    v0.x = rna_tf32(fmaxf(fmaf(v0.x, s0.x, b0.x), 0.f));
    v0.y = rna_tf32(fmaxf(fmaf(v0.y, s0.y, b0.y), 0.f));
    v0.z = rna_tf32(fmaxf(fmaf(v0.z, s0.z, b0.z), 0.f));
    v0.w = rna_tf32(fmaxf(fmaf(v0.w, s0.w, b0.w), 0.f));
    v1.x = rna_tf32(fmaxf(fmaf(v1.x, s1.x, b1.x), 0.f));
    v1.y = rna_tf32(fmaxf(fmaf(v1.y, s1.y, b1.y), 0.f));
    v1.z = rna_tf32(fmaxf(fmaf(v1.z, s1.z, b1.z), 0.f));
    v1.w = rna_tf32(fmaxf(fmaf(v1.w, s1.w, b1.w), 0.f));
    x4[2 * i]     = make_float4(v0.x, v1.x, v0.y, v1.y);
    x4[2 * i + 1] = make_float4(v0.z, v1.z, v0.w, v1.w);
}

// ---------------- elementwise: BN + residual + ReLU -> output ---------------
__global__ void __launch_bounds__(256) apply_res_kernel(
    const float* __restrict__ x, const float* __restrict__ feats,
    float* __restrict__ out)
{
    int i = blockIdx.x * 256 + threadIdx.x;
    if (i >= TOTAL4) return;
    float4 v = ((const float4*)x)[i];
    float4 f = ((const float4*)feats)[i];
    int c4 = i & 31;
    float4 s = ((const float4*)g_scale)[c4];
    float4 b = ((const float4*)g_bias)[c4];
    float4 o;
    o.x = fmaxf(fmaf(v.x, s.x, b.x) + f.x, 0.f);
    o.y = fmaxf(fmaf(v.y, s.y, b.y) + f.y, 0.f);
    o.z = fmaxf(fmaf(v.z, s.z, b.z) + f.z, 0.f);
    o.w = fmaxf(fmaf(v.w, s.w, b.w) + f.w, 0.f);
    ((float4*)out)[i] = o;
}

// ---------------- launch ----------------------------------------------------
extern "C" void kernel_launch(void* const* d_in, const int* in_sizes, int n_in,
                              void* d_out, int out_size) {
    const float* feats  = (const float*)d_in[0];
    const float* W1     = (const float*)d_in[1];
    const float* gamma1 = (const float*)d_in[2];
    const float* beta1  = (const float*)d_in[3];
    const float* W2     = (const float*)d_in[4];
    const float* gamma2 = (const float*)d_in[5];
    const float* beta2  = (const float*)d_in[6];
    const int*   iidx   = (const int*)d_in[7];
    const int*   oidx   = (const int*)d_in[8];
    float* out = (float*)d_out;

    void *pb1, *pb2, *pw1, *pw2;
    cudaGetSymbolAddress(&pb1, g_buf1);
    cudaGetSymbolAddress(&pb2, g_buf2);
    cudaGetSymbolAddress(&pw1, g_wt1);
    cudaGetSymbolAddress(&pw2, g_wt2);
    float* buf1 = (float*)pb1;
    float* buf2 = (float*)pb2;
    float* wt1  = (float*)pw1;
    float* wt2  = (float*)pw2;

    cudaFuncSetAttribute(conv_mma_kernel<false>,
                         cudaFuncAttributeMaxDynamicSharedMemorySize, SMEM_DYN_BYTES);
    cudaFuncSetAttribute(conv_mma_kernel<true>,
                         cudaFuncAttributeMaxDynamicSharedMemorySize, SMEM_DYN_BYTES);

    const int EB4 = (TOTAL4 + 255) / 256;
    const int EB8 = (TOTAL8 + 255) / 256;
    dim3 cgc(NCHUNK, 1);    // center store pass
    dim3 cga(NCHUNK, 26);   // atomic pass (26 non-center offsets)
    dim3 pg(64, NOFF);

    // weight permute/round; rounded+permuted copy of features into buf2
    prep_w_kernel<<<pg, 256>>>(W1, wt1);
    prep_w_kernel<<<pg, 256>>>(W2, wt2);
    round_kernel<<<EB8, 256>>>((const float4*)feats, (float4*)buf2);

    // conv1 (center store, then 26-offset scatter) -> BN1 -> ReLU(+rna+perm)
    conv_mma_kernel<false><<<cgc, 256, SMEM_DYN_BYTES>>>(buf2, wt1, iidx, oidx, buf1);
    conv_mma_kernel<true ><<<cga, 256, SMEM_DYN_BYTES>>>(buf2, wt1, iidx, oidx, buf1);
    bn_stats_kernel<<<NB_STATS, 256>>>(buf1);
    bn_final_kernel<<<1, 512>>>(gamma1, beta1);
    bn_relu_kernel<<<EB8, 256>>>(buf1);

    // conv2 -> BN2 -> +residual -> ReLU
    conv_mma_kernel<false><<<cgc, 256, SMEM_DYN_BYTES>>>(buf1, wt2, iidx, oidx, buf2);
    conv_mma_kernel<true ><<<cga, 256, SMEM_DYN_BYTES>>>(buf1, wt2, iidx, oidx, buf2);
    bn_stats_kernel<<<NB_STATS, 256>>>(buf2);
    bn_final_kernel<<<1, 512>>>(gamma2, beta2);
    apply_res_kernel<<<EB4, 256>>>(buf2, feats, out);
}

// round 13
// speedup vs baseline: 1.3296x; 1.0238x over previous
#include <cuda_runtime.h>
#include <cstdint>

#define N_SITES 200000
#define C 128
#define NOFF 27
#define TOTAL (N_SITES * C)
#define TOTAL4 (TOTAL / 4)
#define TILE_M 128
#define NCHUNK ((N_SITES + TILE_M - 1) / TILE_M)   // 1563
#define STATS_ROWS 512
#define NB_STATS ((N_SITES + STATS_ROWS - 1) / STATS_ROWS)  // 391
#define EPS 1e-4f
#define W_ELEMS (NOFF * C * C)

// smem row stride (floats): 36 ≡ 4 (mod 32) -> conflict-free .32 frag loads
#define LDS_STRIDE 36
#define TILE_FLOATS (TILE_M * LDS_STRIDE)        // 4608 floats = 18.4 KB per operand
#define STAGE_FLOATS (2 * TILE_FLOATS)           // A + B = 9216 floats = 36.9 KB
#define N_STAGES 3
#define SMEM_DYN_BYTES (N_STAGES * STAGE_FLOATS * 4)   // 110592 (3-stage pipeline)

// ---------------- scratch (device globals; no allocations allowed) ----------
__device__ float g_buf1[TOTAL];
__device__ float g_buf2[TOTAL];
__device__ float g_wt1[W_ELEMS];   // [27][co][ci], tf32-rounded
__device__ float g_wt2[W_ELEMS];
__device__ float g_part[NB_STATS * C * 2];
__device__ float g_scale[C];
__device__ float g_bias[C];

// ---------------- helpers ----------------------------------------------------
__device__ __forceinline__ uint32_t smem_u32(const void* p) {
    uint32_t a;
    asm("{ .reg .u64 t; cvta.to.shared.u64 t, %1; cvt.u32.u64 %0, t; }" : "=r"(a) : "l"(p));
    return a;
}
__device__ __forceinline__ float rna_tf32(float x) {
    float r;
    asm("cvt.rna.tf32.f32 %0, %1;" : "=f"(r) : "f"(x));
    return r;
}
__device__ __forceinline__ void red_add2(float* p, float a, float b) {
    asm volatile("red.global.add.v2.f32 [%0], {%1, %2};"
                 :: "l"(p), "f"(a), "f"(b) : "memory");
}
__device__ __forceinline__ void st2(float* p, float a, float b) {
    asm volatile("st.global.v2.f32 [%0], {%1, %2};"
                 :: "l"(p), "f"(a), "f"(b) : "memory");
}
// L2-only variant for gathered feature rows (no L1 reuse)
__device__ __forceinline__ void cp_async16_cg(uint32_t dst, const void* src, int src_bytes) {
    asm volatile("cp.async.cg.shared.global [%0], [%1], 16, %2;"
                 :: "r"(dst), "l"(src), "r"(src_bytes) : "memory");
}
// L1-caching variant for weights (reused across tiles of the same offset)
__device__ __forceinline__ void cp_async16_ca(uint32_t dst, const void* src) {
    asm volatile("cp.async.ca.shared.global [%0], [%1], 16;"
                 :: "r"(dst), "l"(src) : "memory");
}
#define CP_COMMIT() asm volatile("cp.async.commit_group;" ::: "memory")
#define CP_WAIT(n)  asm volatile("cp.async.wait_group %0;" :: "n"(n) : "memory")

__device__ __forceinline__ void mma_tf32(float* d, const uint32_t* a, const uint32_t* b) {
    asm volatile(
        "mma.sync.aligned.m16n8k8.row.col.f32.tf32.tf32.f32 "
        "{%0,%1,%2,%3}, {%4,%5,%6,%7}, {%8,%9}, {%0,%1,%2,%3};"
        : "+f"(d[0]), "+f"(d[1]), "+f"(d[2]), "+f"(d[3])
        : "r"(a[0]), "r"(a[1]), "r"(a[2]), "r"(a[3]), "r"(b[0]), "r"(b[1]));
}

// ---- prep: transpose W[k][ci][co] -> Wt[k][co][ci], rna round ---------------
__global__ void __launch_bounds__(256) prep_w_kernel(const float* __restrict__ W,
                                                     float* __restrict__ Wt) {
    const int k = blockIdx.y;
    const int idx = blockIdx.x * 256 + threadIdx.x;  // over 16384
    const int ci = idx >> 7;
    const int co = idx & 127;
    float v = __ldg(&W[(long)k * 16384 + ci * 128 + co]);  // coalesced read
    Wt[(long)k * 16384 + co * 128 + ci] = rna_tf32(v);
}

// ---- one-shot rna rounding of features --------------------------------------
__global__ void __launch_bounds__(256) round_kernel(const float4* __restrict__ src,
                                                    float4* __restrict__ dst) {
    int i = blockIdx.x * 256 + threadIdx.x;
    if (i >= TOTAL4) return;
    float4 v = __ldg(&src[i]);
    v.x = rna_tf32(v.x); v.y = rna_tf32(v.y);
    v.z = rna_tf32(v.z); v.w = rna_tf32(v.w);
    dst[i] = v;
}

// ---- tf32 mma.sync pair-tile conv (3-stage cp.async pipeline) ---------------
// Tile: 128 pairs x 128 outch x K=128, K chunked by 32.
// ATOMIC=false: center offset (k=13), plain stores (no zero pass needed).
// ATOMIC=true : 26 remaining offsets, red.global scatter-add.
template <bool ATOMIC>
__global__ void __launch_bounds__(256, 2) conv_mma_kernel(
    const float* __restrict__ feats, const float* __restrict__ Wt,
    const int* __restrict__ in_idx, const int* __restrict__ out_idx,
    float* __restrict__ out)
{
    extern __shared__ float dsm[];
    __shared__ int s_ii[TILE_M];
    __shared__ int s_oi[TILE_M];

    const int k = ATOMIC ? (blockIdx.y + (blockIdx.y >= 13 ? 1 : 0)) : 13;
    const long base = (long)blockIdx.x * TILE_M;
    const int* ik = in_idx + (long)k * N_SITES;
    if (ATOMIC && __ldg(&ik[base]) >= N_SITES) return;  // fully-padded chunk
    const int* ok = out_idx + (long)k * N_SITES;

    const int tid = threadIdx.x;
    const int wid = tid >> 5;
    const int lane = tid & 31;
    const int g = lane >> 2;       // group id (row within frag)
    const int tig = lane & 3;      // thread in group

    if (tid < TILE_M) {
        long p = base + tid;
        bool v = (p < N_SITES);
        s_ii[tid] = v ? __ldg(&ik[p]) : N_SITES;
        s_oi[tid] = v ? __ldg(&ok[p]) : N_SITES;
    }
    __syncthreads();

    const int warp_m = wid & 3;    // 0..3 -> 32-row band
    const int warp_n = wid >> 2;   // 0..1 -> 64-col band
    const int m0 = warp_m * 32;
    const int n0 = warp_n * 64;

    float acc[2][8][4];
    #pragma unroll
    for (int mf = 0; mf < 2; mf++)
        #pragma unroll
        for (int nf = 0; nf < 8; nf++)
            #pragma unroll
            for (int r = 0; r < 4; r++) acc[mf][nf][r] = 0.f;

    const float4* f4 = (const float4*)feats;
    const float4* w4 = (const float4*)(Wt + (long)k * 16384);
    const int r_st = tid >> 3;          // staging row base
    const int g4 = tid & 7;             // float4 granule within 32-float row

    const uint32_t dsm_base = smem_u32(dsm);

    // ---- stage A+B chunk kc into pipeline buffer pb via cp.async ------------
    auto stage = [&](int kc, int pb) {
        const uint32_t a_u32 = dsm_base + pb * (STAGE_FLOATS * 4);
        const uint32_t b_u32 = a_u32 + TILE_FLOATS * 4;
        #pragma unroll
        for (int it = 0; it < 4; it++) {
            int r = r_st + it * 32;
            int ii = s_ii[r];
            bool v = (ii < N_SITES);
            const float4* src = f4 + (long)(v ? ii : 0) * 32 + kc * 8 + g4;
            cp_async16_cg(a_u32 + r * (LDS_STRIDE * 4) + g4 * 16, src, v ? 16 : 0);
        }
        #pragma unroll
        for (int it = 0; it < 4; it++) {
            int r = r_st + it * 32;
            cp_async16_ca(b_u32 + r * (LDS_STRIDE * 4) + g4 * 16,
                          w4 + r * 32 + kc * 8 + g4);
        }
    };

    // ---- compute on pipeline buffer pb (frag loads are LDS.32) --------------
    auto compute = [&](int pb) {
        const float* Asb = dsm + pb * STAGE_FLOATS;
        const float* Bsb = Asb + TILE_FLOATS;
        #pragma unroll
        for (int ks = 0; ks < 4; ks++) {
            const int kk = ks * 8;
            uint32_t b[8][2];
            #pragma unroll
            for (int nf = 0; nf < 8; nf++) {
                const int n = n0 + nf * 8 + g;
                b[nf][0] = __float_as_uint(Bsb[n * LDS_STRIDE + kk + tig]);
                b[nf][1] = __float_as_uint(Bsb[n * LDS_STRIDE + kk + tig + 4]);
            }
            #pragma unroll
            for (int mf = 0; mf < 2; mf++) {
                const int row = m0 + mf * 16 + g;
                uint32_t a[4];
                a[0] = __float_as_uint(Asb[row * LDS_STRIDE + kk + tig]);
                a[1] = __float_as_uint(Asb[(row + 8) * LDS_STRIDE + kk + tig]);
                a[2] = __float_as_uint(Asb[row * LDS_STRIDE + kk + tig + 4]);
                a[3] = __float_as_uint(Asb[(row + 8) * LDS_STRIDE + kk + tig + 4]);
                #pragma unroll
                for (int nf = 0; nf < 8; nf++)
                    mma_tf32(acc[mf][nf], a, b[nf]);
            }
        }
    };

    // ---- 3-stage software pipeline over 4 K-chunks ---------------------------
    // iter kc: WAIT(chunk kc landed) -> sync (retire buf readers) ->
    //          stage(kc+2) into freed buffer -> compute(kc)
    stage(0, 0); CP_COMMIT();
    stage(1, 1); CP_COMMIT();
    #pragma unroll
    for (int kc = 0; kc < 4; kc++) {
        if (kc < 3) { CP_WAIT(1); } else { CP_WAIT(0); }
        __syncthreads();
        if (kc + 2 <= 3) {
            stage(kc + 2, (kc + 2) % N_STAGES);
            CP_COMMIT();
        }
        compute(kc % N_STAGES);
    }

    // ---- epilogue: rows -> out[oi] ------------------------------------------
    #pragma unroll
    for (int mf = 0; mf < 2; mf++) {
        const int r_lo = m0 + mf * 16 + g;
        const int oi_lo = s_oi[r_lo];
        const int oi_hi = s_oi[r_lo + 8];
        #pragma unroll
        for (int nf = 0; nf < 8; nf++) {
            const int col = n0 + nf * 8 + 2 * tig;
            if (oi_lo < N_SITES) {
                float* p = out + (long)oi_lo * C + col;
                if (ATOMIC) red_add2(p, acc[mf][nf][0], acc[mf][nf][1]);
                else        st2(p, acc[mf][nf][0], acc[mf][nf][1]);
            }
            if (oi_hi < N_SITES) {
                float* p = out + (long)oi_hi * C + col;
                if (ATOMIC) red_add2(p, acc[mf][nf][2], acc[mf][nf][3]);
                else        st2(p, acc[mf][nf][2], acc[mf][nf][3]);
            }
        }
    }
}

// ---------------- BN stats: per-block partial sum / sumsq per channel -------
__global__ void __launch_bounds__(256) bn_stats_kernel(const float* __restrict__ x) {
    const int b = blockIdx.x;
    const int r0 = b * STATS_ROWS;
    const int r1 = min(r0 + STATS_ROWS, N_SITES);
    const int c = threadIdx.x & 127;
    const int half = threadIdx.x >> 7;

    float s = 0.f, ss = 0.f;
    for (int r = r0 + half; r < r1; r += 2) {
        float v = __ldg(&x[(long)r * C + c]);
        s += v;
        ss += v * v;
    }
    __shared__ float sm[512];
    sm[threadIdx.x] = s;
    sm[256 + threadIdx.x] = ss;
    __syncthreads();
    if (half == 0) {
        g_part[((long)b * C + c) * 2 + 0] = s + sm[threadIdx.x + 128];
        g_part[((long)b * C + c) * 2 + 1] = ss + sm[256 + threadIdx.x + 128];
    }
}

// fixed-order finalize (4 workers per channel): deterministic mean/var
__global__ void __launch_bounds__(512) bn_final_kernel(const float* __restrict__ gamma,
                                                       const float* __restrict__ beta) {
    const int c = threadIdx.x & 127;
    const int w = threadIdx.x >> 7;  // 0..3
    float s = 0.f, ss = 0.f;
    for (int b = w; b < NB_STATS; b += 4) {
        s  += g_part[((long)b * C + c) * 2 + 0];
        ss += g_part[((long)b * C + c) * 2 + 1];
    }
    __shared__ float sm[1024];
    sm[threadIdx.x] = s;
    sm[512 + threadIdx.x] = ss;
    __syncthreads();
    if (w == 0) {
        #pragma unroll
        for (int j = 1; j < 4; j++) {
            s  += sm[j * 128 + c];
            ss += sm[512 + j * 128 + c];
        }
        const float inv_n = 1.f / (float)N_SITES;
        float m = s * inv_n;
        float v = ss * inv_n - m * m;
        float sc = gamma[c] * rsqrtf(v + EPS);
        g_scale[c] = sc;
        g_bias[c] = beta[c] - m * sc;
    }
}

// ---- elementwise: in-place BN + ReLU + rna (conv2 input) --------------------
__global__ void __launch_bounds__(256) bn_relu_kernel(float* __restrict__ x) {
    int i = blockIdx.x * 256 + threadIdx.x;
    if (i >= TOTAL4) return;
    float4 v = ((const float4*)x)[i];
    int c4 = i & 31;
    float4 s = ((const float4*)g_scale)[c4];
    float4 b = ((const float4*)g_bias)[c4];
    float4 o;
    o.x = rna_tf32(fmaxf(fmaf(v.x, s.x, b.x), 0.f));
    o.y = rna_tf32(fmaxf(fmaf(v.y, s.y, b.y), 0.f));
    o.z = rna_tf32(fmaxf(fmaf(v.z, s.z, b.z), 0.f));
    o.w = rna_tf32(fmaxf(fmaf(v.w, s.w, b.w), 0.f));
    ((float4*)x)[i] = o;
}

// ---------------- elementwise: BN + residual + ReLU -> output ---------------
__global__ void __launch_bounds__(256) apply_res_kernel(
    const float* __restrict__ x, const float* __restrict__ feats,
    float* __restrict__ out)
{
    int i = blockIdx.x * 256 + threadIdx.x;
    if (i >= TOTAL4) return;
    float4 v = ((const float4*)x)[i];
    float4 f = ((const float4*)feats)[i];
    int c4 = i & 31;
    float4 s = ((const float4*)g_scale)[c4];
    float4 b = ((const float4*)g_bias)[c4];
    float4 o;
    o.x = fmaxf(fmaf(v.x, s.x, b.x) + f.x, 0.f);
    o.y = fmaxf(fmaf(v.y, s.y, b.y) + f.y, 0.f);
    o.z = fmaxf(fmaf(v.z, s.z, b.z) + f.z, 0.f);
    o.w = fmaxf(fmaf(v.w, s.w, b.w) + f.w, 0.f);
    ((float4*)out)[i] = o;
}

// ---------------- launch ----------------------------------------------------
extern "C" void kernel_launch(void* const* d_in, const int* in_sizes, int n_in,
                              void* d_out, int out_size) {
    const float* feats  = (const float*)d_in[0];
    const float* W1     = (const float*)d_in[1];
    const float* gamma1 = (const float*)d_in[2];
    const float* beta1  = (const float*)d_in[3];
    const float* W2     = (const float*)d_in[4];
    const float* gamma2 = (const float*)d_in[5];
    const float* beta2  = (const float*)d_in[6];
    const int*   iidx   = (const int*)d_in[7];
    const int*   oidx   = (const int*)d_in[8];
    float* out = (float*)d_out;

    void *pb1, *pb2, *pw1, *pw2;
    cudaGetSymbolAddress(&pb1, g_buf1);
    cudaGetSymbolAddress(&pb2, g_buf2);
    cudaGetSymbolAddress(&pw1, g_wt1);
    cudaGetSymbolAddress(&pw2, g_wt2);
    float* buf1 = (float*)pb1;
    float* buf2 = (float*)pb2;
    float* wt1  = (float*)pw1;
    float* wt2  = (float*)pw2;

    cudaFuncSetAttribute(conv_mma_kernel<false>,
                         cudaFuncAttributeMaxDynamicSharedMemorySize, SMEM_DYN_BYTES);
    cudaFuncSetAttribute(conv_mma_kernel<true>,
                         cudaFuncAttributeMaxDynamicSharedMemorySize, SMEM_DYN_BYTES);

    const int EB4 = (TOTAL4 + 255) / 256;
    dim3 cgc(NCHUNK, 1);    // center store pass
    dim3 cga(NCHUNK, 26);   // atomic pass (26 non-center offsets)
    dim3 pg(64, NOFF);

    // weight transpose + tf32 rounding; rounded copy of features into buf2
    prep_w_kernel<<<pg, 256>>>(W1, wt1);
    prep_w_kernel<<<pg, 256>>>(W2, wt2);
    round_kernel<<<EB4, 256>>>((const float4*)feats, (float4*)buf2);

    // conv1 (center store, then 26-offset scatter) -> BN1 -> ReLU(+rna)
    conv_mma_kernel<false><<<cgc, 256, SMEM_DYN_BYTES>>>(buf2, wt1, iidx, oidx, buf1);
    conv_mma_kernel<true ><<<cga, 256, SMEM_DYN_BYTES>>>(buf2, wt1, iidx, oidx, buf1);
    bn_stats_kernel<<<NB_STATS, 256>>>(buf1);
    bn_final_kernel<<<1, 512>>>(gamma1, beta1);
    bn_relu_kernel<<<EB4, 256>>>(buf1);

    // conv2 -> BN2 -> +residual -> ReLU
    conv_mma_kernel<false><<<cgc, 256, SMEM_DYN_BYTES>>>(buf1, wt2, iidx, oidx, buf2);
    conv_mma_kernel<true ><<<cga, 256, SMEM_DYN_BYTES>>>(buf1, wt2, iidx, oidx, buf2);
    bn_stats_kernel<<<NB_STATS, 256>>>(buf2);
    bn_final_kernel<<<1, 512>>>(gamma2, beta2);
    apply_res_kernel<<<EB4, 256>>>(buf2, feats, out);
}

// round 16
// speedup vs baseline: 1.4157x; 1.0648x over previous
#include <cuda_runtime.h>
#include <cuda_fp16.h>
#include <cstdint>

#define N_SITES 200000
#define C 128
#define NOFF 27
#define TOTAL (N_SITES * C)
#define TOTAL4 (TOTAL / 4)
#define TOTAL8 (TOTAL / 8)
#define TILE_M 128
#define NCHUNK ((N_SITES + TILE_M - 1) / TILE_M)   // 1563
#define STATS_ROWS 512
#define NB_STATS ((N_SITES + STATS_ROWS - 1) / STATS_ROWS)  // 391
#define EPS 1e-4f
#define W_ELEMS (NOFF * C * C)

// fp16 tile: rows of 32 halves (64 B) padded to 80 B (20 words).
// sigma=20 ≡ 4 (mod 8): frag-load lanes g*20+tig cover all 32 banks. Verified.
#define ROW_WORDS 20
#define TILE_WORDS (TILE_M * ROW_WORDS)          // 2560 words = 10 KB / operand
#define STAGE_WORDS (2 * TILE_WORDS)             // A + B = 20 KB
#define N_STAGES 4
#define SMEM_DYN_BYTES (N_STAGES * STAGE_WORDS * 4)   // 81920

// ---------------- scratch (device globals; no allocations allowed) ----------
__device__ float g_buf1[TOTAL];
__device__ float g_buf2[TOTAL];
__device__ __half g_h[TOTAL];       // fp16 conv input (round() then bn_relu())
__device__ __half g_wt1[W_ELEMS];   // [27][co][ci], fp16
__device__ __half g_wt2[W_ELEMS];
__device__ float g_part[NB_STATS * C * 2];
__device__ float g_scale[C];
__device__ float g_bias[C];

// ---------------- helpers ----------------------------------------------------
__device__ __forceinline__ uint32_t h2_u32(__half2 h) {
    return *reinterpret_cast<uint32_t*>(&h);
}
__device__ __forceinline__ uint32_t smem_u32(const void* p) {
    uint32_t a;
    asm("{ .reg .u64 t; cvta.to.shared.u64 t, %1; cvt.u32.u64 %0, t; }" : "=r"(a) : "l"(p));
    return a;
}
__device__ __forceinline__ void red_add2(float* p, float a, float b) {
    asm volatile("red.global.add.v2.f32 [%0], {%1, %2};"
                 :: "l"(p), "f"(a), "f"(b) : "memory");
}
__device__ __forceinline__ void st2(float* p, float a, float b) {
    asm volatile("st.global.v2.f32 [%0], {%1, %2};"
                 :: "l"(p), "f"(a), "f"(b) : "memory");
}
// L2-only variant for gathered feature rows (no L1 reuse)
__device__ __forceinline__ void cp_async16_cg(uint32_t dst, const void* src, int src_bytes) {
    asm volatile("cp.async.cg.shared.global [%0], [%1], 16, %2;"
                 :: "r"(dst), "l"(src), "r"(src_bytes) : "memory");
}
// L1-caching variant for weights (reused across tiles of the same offset)
__device__ __forceinline__ void cp_async16_ca(uint32_t dst, const void* src) {
    asm volatile("cp.async.ca.shared.global [%0], [%1], 16;"
                 :: "r"(dst), "l"(src) : "memory");
}
#define CP_COMMIT() asm volatile("cp.async.commit_group;" ::: "memory")
#define CP_WAIT(n)  asm volatile("cp.async.wait_group %0;" :: "n"(n) : "memory")

__device__ __forceinline__ void mma_f16(float* d, const uint32_t* a, const uint32_t* b) {
    asm volatile(
        "mma.sync.aligned.m16n8k16.row.col.f32.f16.f16.f32 "
        "{%0,%1,%2,%3}, {%4,%5,%6,%7}, {%8,%9}, {%0,%1,%2,%3};"
        : "+f"(d[0]), "+f"(d[1]), "+f"(d[2]), "+f"(d[3])
        : "r"(a[0]), "r"(a[1]), "r"(a[2]), "r"(a[3]), "r"(b[0]), "r"(b[1]));
}

// ---- prep: transpose W[k][ci][co] -> Wt[k][co][ci], fp16 --------------------
__global__ void __launch_bounds__(256) prep_w_kernel(const float* __restrict__ W,
                                                     __half* __restrict__ Wt) {
    const int k = blockIdx.y;
    const int idx = blockIdx.x * 256 + threadIdx.x;  // over 16384
    const int ci = idx >> 7;
    const int co = idx & 127;
    float v = __ldg(&W[(long)k * 16384 + ci * 128 + co]);  // coalesced read
    Wt[(long)k * 16384 + co * 128 + ci] = __float2half_rn(v);
}

// ---- one-shot fp16 conversion of features -----------------------------------
__global__ void __launch_bounds__(256) round_kernel(const float4* __restrict__ src,
                                                    __half* __restrict__ dst) {
    int i = blockIdx.x * 256 + threadIdx.x;   // over TOTAL8
    if (i >= TOTAL8) return;
    float4 v0 = __ldg(&src[2 * i]);
    float4 v1 = __ldg(&src[2 * i + 1]);
    uint4 o;
    o.x = h2_u32(__floats2half2_rn(v0.x, v0.y));
    o.y = h2_u32(__floats2half2_rn(v0.z, v0.w));
    o.z = h2_u32(__floats2half2_rn(v1.x, v1.y));
    o.w = h2_u32(__floats2half2_rn(v1.z, v1.w));
    *(uint4*)(dst + 8 * (long)i) = o;
}

// ---- fp16 mma.sync pair-tile conv: all 4 K-chunks prefetched ----------------
// Tile: 128 pairs x 128 outch x K=128 (4 chunks of 32 halves).
// ATOMIC=false: center offset (k=13), plain stores (no zero pass needed).
// ATOMIC=true : 26 remaining offsets, red.global scatter-add.
template <bool ATOMIC>
__global__ void __launch_bounds__(256, 2) conv_mma_kernel(
    const __half* __restrict__ feats, const __half* __restrict__ Wt,
    const int* __restrict__ in_idx, const int* __restrict__ out_idx,
    float* __restrict__ out)
{
    extern __shared__ uint32_t dsm[];
    __shared__ int s_ii[TILE_M];
    __shared__ int s_oi[TILE_M];

    const int k = ATOMIC ? (blockIdx.y + (blockIdx.y >= 13 ? 1 : 0)) : 13;
    const long base = (long)blockIdx.x * TILE_M;
    const int* ik = in_idx + (long)k * N_SITES;
    if (ATOMIC && __ldg(&ik[base]) >= N_SITES) return;  // fully-padded chunk
    const int* ok = out_idx + (long)k * N_SITES;

    const int tid = threadIdx.x;
    const int wid = tid >> 5;
    const int lane = tid & 31;
    const int g = lane >> 2;       // group id (row within frag)
    const int tig = lane & 3;      // thread in group

    if (tid < TILE_M) {
        long p = base + tid;
        bool v = (p < N_SITES);
        s_ii[tid] = v ? __ldg(&ik[p]) : N_SITES;
        s_oi[tid] = v ? __ldg(&ok[p]) : N_SITES;
    }
    __syncthreads();

    const int warp_m = wid & 3;    // 0..3 -> 32-row band
    const int warp_n = wid >> 2;   // 0..1 -> 64-col band
    const int m0 = warp_m * 32;
    const int n0 = warp_n * 64;

    float acc[2][8][4];
    #pragma unroll
    for (int mf = 0; mf < 2; mf++)
        #pragma unroll
        for (int nf = 0; nf < 8; nf++)
            #pragma unroll
            for (int r = 0; r < 4; r++) acc[mf][nf][r] = 0.f;

    const char* fh = (const char*)feats;                 // row = 256 B
    const char* wh = (const char*)(Wt + (long)k * 16384);
    const uint32_t dsm_base = smem_u32(dsm);

    // ---- stage A+B chunk kc into buffer pb (warp-along-rows: bank-clean) ----
    auto stage = [&](int kc, int pb) {
        const uint32_t a_u32 = dsm_base + pb * (STAGE_WORDS * 4);
        const uint32_t b_u32 = a_u32 + TILE_WORDS * 4;
        #pragma unroll
        for (int it = 0; it < 2; it++) {
            int idx = tid + it * 256;      // 512 granules: r = idx&127, g4 = idx>>7
            int r = idx & 127, g4 = idx >> 7;
            int ii = s_ii[r];
            bool v = (ii < N_SITES);
            const char* src = fh + (long)(v ? ii : 0) * 256 + kc * 64 + g4 * 16;
            cp_async16_cg(a_u32 + (r * ROW_WORDS + g4 * 4) * 4, src, v ? 16 : 0);
        }
        #pragma unroll
        for (int it = 0; it < 2; it++) {
            int idx = tid + it * 256;
            int r = idx & 127, g4 = idx >> 7;
            cp_async16_ca(b_u32 + (r * ROW_WORDS + g4 * 4) * 4,
                          wh + r * 256 + kc * 64 + g4 * 16);
        }
    };

    // ---- compute on buffer pb: 2 K=16 mma steps per chunk -------------------
    auto compute = [&](int pb) {
        const uint32_t* Asb = dsm + pb * STAGE_WORDS;
        const uint32_t* Bsb = Asb + TILE_WORDS;
        #pragma unroll
        for (int ks2 = 0; ks2 < 2; ks2++) {
            const int kw = ks2 * 8;        // word offset within 20-word row
            uint32_t b[8][2];
            #pragma unroll
            for (int nf = 0; nf < 8; nf++) {
                const int n = n0 + nf * 8 + g;
                b[nf][0] = Bsb[n * ROW_WORDS + kw + tig];
                b[nf][1] = Bsb[n * ROW_WORDS + kw + tig + 4];
            }
            #pragma unroll
            for (int mf = 0; mf < 2; mf++) {
                const int row = m0 + mf * 16 + g;
                uint32_t a[4];
                a[0] = Asb[row * ROW_WORDS + kw + tig];
                a[1] = Asb[(row + 8) * ROW_WORDS + kw + tig];
                a[2] = Asb[row * ROW_WORDS + kw + tig + 4];
                a[3] = Asb[(row + 8) * ROW_WORDS + kw + tig + 4];
                #pragma unroll
                for (int nf = 0; nf < 8; nf++)
                    mma_f16(acc[mf][nf], a, b[nf]);
            }
        }
    };

    // ---- prefetch ALL 4 chunks, then wait->bar->compute each ----------------
    stage(0, 0); CP_COMMIT();
    stage(1, 1); CP_COMMIT();
    stage(2, 2); CP_COMMIT();
    stage(3, 3); CP_COMMIT();
    CP_WAIT(3); __syncthreads(); compute(0);
    CP_WAIT(2); __syncthreads(); compute(1);
    CP_WAIT(1); __syncthreads(); compute(2);
    CP_WAIT(0); __syncthreads(); compute(3);

    // ---- epilogue: rows -> out[oi] ------------------------------------------
    #pragma unroll
    for (int mf = 0; mf < 2; mf++) {
        const int r_lo = m0 + mf * 16 + g;
        const int oi_lo = s_oi[r_lo];
        const int oi_hi = s_oi[r_lo + 8];
        #pragma unroll
        for (int nf = 0; nf < 8; nf++) {
            const int col = n0 + nf * 8 + 2 * tig;
            if (oi_lo < N_SITES) {
                float* p = out + (long)oi_lo * C + col;
                if (ATOMIC) red_add2(p, acc[mf][nf][0], acc[mf][nf][1]);
                else        st2(p, acc[mf][nf][0], acc[mf][nf][1]);
            }
            if (oi_hi < N_SITES) {
                float* p = out + (long)oi_hi * C + col;
                if (ATOMIC) red_add2(p, acc[mf][nf][2], acc[mf][nf][3]);
                else        st2(p, acc[mf][nf][2], acc[mf][nf][3]);
            }
        }
    }
}

// ---------------- BN stats: per-block partial sum / sumsq per channel -------
__global__ void __launch_bounds__(256) bn_stats_kernel(const float* __restrict__ x) {
    const int b = blockIdx.x;
    const int r0 = b * STATS_ROWS;
    const int r1 = min(r0 + STATS_ROWS, N_SITES);
    const int c = threadIdx.x & 127;
    const int half = threadIdx.x >> 7;

    float s = 0.f, ss = 0.f;
    for (int r = r0 + half; r < r1; r += 2) {
        float v = __ldg(&x[(long)r * C + c]);
        s += v;
        ss += v * v;
    }
    __shared__ float sm[512];
    sm[threadIdx.x] = s;
    sm[256 + threadIdx.x] = ss;
    __syncthreads();
    if (half == 0) {
        g_part[((long)b * C + c) * 2 + 0] = s + sm[threadIdx.x + 128];
        g_part[((long)b * C + c) * 2 + 1] = ss + sm[256 + threadIdx.x + 128];
    }
}

// fixed-order finalize (4 workers per channel): deterministic mean/var
__global__ void __launch_bounds__(512) bn_final_kernel(const float* __restrict__ gamma,
                                                       const float* __restrict__ beta) {
    const int c = threadIdx.x & 127;
    const int w = threadIdx.x >> 7;  // 0..3
    float s = 0.f, ss = 0.f;
    for (int b = w; b < NB_STATS; b += 4) {
        s  += g_part[((long)b * C + c) * 2 + 0];
        ss += g_part[((long)b * C + c) * 2 + 1];
    }
    __shared__ float sm[1024];
    sm[threadIdx.x] = s;
    sm[512 + threadIdx.x] = ss;
    __syncthreads();
    if (w == 0) {
        #pragma unroll
        for (int j = 1; j < 4; j++) {
            s  += sm[j * 128 + c];
            ss += sm[512 + j * 128 + c];
        }
        const float inv_n = 1.f / (float)N_SITES;
        float m = s * inv_n;
        float v = ss * inv_n - m * m;
        float sc = gamma[c] * rsqrtf(v + EPS);
        g_scale[c] = sc;
        g_bias[c] = beta[c] - m * sc;
    }
}

// ---- elementwise: BN + ReLU, emit fp16 only (conv2 input) -------------------
__global__ void __launch_bounds__(256) bn_relu_kernel(const float* __restrict__ x,
                                                      __half* __restrict__ dst) {
    int i = blockIdx.x * 256 + threadIdx.x;   // over TOTAL4
    if (i >= TOTAL4) return;
    float4 v = ((const float4*)x)[i];
    int c4 = i & 31;
    float4 s = ((const float4*)g_scale)[c4];
    float4 b = ((const float4*)g_bias)[c4];
    float ox = fmaxf(fmaf(v.x, s.x, b.x), 0.f);
    float oy = fmaxf(fmaf(v.y, s.y, b.y), 0.f);
    float oz = fmaxf(fmaf(v.z, s.z, b.z), 0.f);
    float ow = fmaxf(fmaf(v.w, s.w, b.w), 0.f);
    uint2 o;
    o.x = h2_u32(__floats2half2_rn(ox, oy));
    o.y = h2_u32(__floats2half2_rn(oz, ow));
    *(uint2*)(dst + 4 * (long)i) = o;
}

// ---------------- elementwise: BN + residual + ReLU -> output ---------------
__global__ void __launch_bounds__(256) apply_res_kernel(
    const float* __restrict__ x, const float* __restrict__ feats,
    float* __restrict__ out)
{
    int i = blockIdx.x * 256 + threadIdx.x;
    if (i >= TOTAL4) return;
    float4 v = ((const float4*)x)[i];
    float4 f = ((const float4*)feats)[i];
    int c4 = i & 31;
    float4 s = ((const float4*)g_scale)[c4];
    float4 b = ((const float4*)g_bias)[c4];
    float4 o;
    o.x = fmaxf(fmaf(v.x, s.x, b.x) + f.x, 0.f);
    o.y = fmaxf(fmaf(v.y, s.y, b.y) + f.y, 0.f);
    o.z = fmaxf(fmaf(v.z, s.z, b.z) + f.z, 0.f);
    o.w = fmaxf(fmaf(v.w, s.w, b.w) + f.w, 0.f);
    ((float4*)out)[i] = o;
}

// ---------------- launch ----------------------------------------------------
extern "C" void kernel_launch(void* const* d_in, const int* in_sizes, int n_in,
                              void* d_out, int out_size) {
    const float* feats  = (const float*)d_in[0];
    const float* W1     = (const float*)d_in[1];
    const float* gamma1 = (const float*)d_in[2];
    const float* beta1  = (const float*)d_in[3];
    const float* W2     = (const float*)d_in[4];
    const float* gamma2 = (const float*)d_in[5];
    const float* beta2  = (const float*)d_in[6];
    const int*   iidx   = (const int*)d_in[7];
    const int*   oidx   = (const int*)d_in[8];
    float* out = (float*)d_out;

    void *pb1, *pb2, *ph, *pw1, *pw2;
    cudaGetSymbolAddress(&pb1, g_buf1);
    cudaGetSymbolAddress(&pb2, g_buf2);
    cudaGetSymbolAddress(&ph,  g_h);
    cudaGetSymbolAddress(&pw1, g_wt1);
    cudaGetSymbolAddress(&pw2, g_wt2);
    float*  buf1 = (float*)pb1;
    float*  buf2 = (float*)pb2;
    __half* fh   = (__half*)ph;
    __half* wt1  = (__half*)pw1;
    __half* wt2  = (__half*)pw2;

    cudaFuncSetAttribute(conv_mma_kernel<false>,
                         cudaFuncAttributeMaxDynamicSharedMemorySize, SMEM_DYN_BYTES);
    cudaFuncSetAttribute(conv_mma_kernel<true>,
                         cudaFuncAttributeMaxDynamicSharedMemorySize, SMEM_DYN_BYTES);

    const int EB4 = (TOTAL4 + 255) / 256;
    const int EB8 = (TOTAL8 + 255) / 256;
    dim3 cgc(NCHUNK, 1);    // center store pass
    dim3 cga(NCHUNK, 26);   // atomic pass (26 non-center offsets)
    dim3 pg(64, NOFF);

    // weight transpose -> fp16; fp16 copy of features
    prep_w_kernel<<<pg, 256>>>(W1, wt1);
    prep_w_kernel<<<pg, 256>>>(W2, wt2);
    round_kernel<<<EB8, 256>>>((const float4*)feats, fh);

    // conv1 (center store, then 26-offset scatter) -> BN1 -> ReLU -> fp16
    conv_mma_kernel<false><<<cgc, 256, SMEM_DYN_BYTES>>>(fh, wt1, iidx, oidx, buf1);
    conv_mma_kernel<true ><<<cga, 256, SMEM_DYN_BYTES>>>(fh, wt1, iidx, oidx, buf1);
    bn_stats_kernel<<<NB_STATS, 256>>>(buf1);
    bn_final_kernel<<<1, 512>>>(gamma1, beta1);
    bn_relu_kernel<<<EB4, 256>>>(buf1, fh);

    // conv2 -> BN2 -> +residual -> ReLU
    conv_mma_kernel<false><<<cgc, 256, SMEM_DYN_BYTES>>>(fh, wt2, iidx, oidx, buf2);
    conv_mma_kernel<true ><<<cga, 256, SMEM_DYN_BYTES>>>(fh, wt2, iidx, oidx, buf2);
    bn_stats_kernel<<<NB_STATS, 256>>>(buf2);
    bn_final_kernel<<<1, 512>>>(gamma2, beta2);
    apply_res_kernel<<<EB4, 256>>>(buf2, feats, out);
}

// round 17
// speedup vs baseline: 1.8541x; 1.3097x over previous
#include <cuda_runtime.h>
#include <cuda_fp16.h>
#include <cstdint>

#define N_SITES 200000
#define C 128
#define NOFF 27
#define TOTAL (N_SITES * C)
#define TOTAL4 (TOTAL / 4)
#define TOTAL8 (TOTAL / 8)
#define TILE_M 128
#define NCHUNK ((N_SITES + TILE_M - 1) / TILE_M)   // 1563
#define TPB 4                                       // tiles per CTA (B resident)
#define NGROUP ((NCHUNK + TPB - 1) / TPB)           // 391
#define STATS_ROWS 512
#define NB_STATS ((N_SITES + STATS_ROWS - 1) / STATS_ROWS)  // 391
#define EPS 1e-4f
#define W_ELEMS (NOFF * C * C)

// B resident: 128 rows x 128 halves (64 words) padded to 68 words.
//   frag banks: (68n + tig) mod 32 -> (4g + tig) distinct. Verified.
#define B_ROW_WORDS 68
#define B_WORDS (TILE_M * B_ROW_WORDS)            // 8704 words = 34816 B
// A chunk buffers: rows of 32 halves (16 words) padded to 20.
//   frag banks: (20r + tig) mod 32 -> {0,20,8,28,16,4,24,12}+tig distinct.
#define A_ROW_WORDS 20
#define A_CHUNK_WORDS (TILE_M * A_ROW_WORDS)      // 2560 words = 10 KB
#define N_ABUF 4
#define SMEM_DYN_BYTES ((B_WORDS + N_ABUF * A_CHUNK_WORDS) * 4)   // 75776

// ---------------- scratch (device globals; no allocations allowed) ----------
__device__ float g_buf1[TOTAL];
__device__ float g_buf2[TOTAL];
__device__ __half g_h[TOTAL];       // fp16 conv input (round() then bn_relu())
__device__ __half g_wt1[W_ELEMS];   // [27][co][ci], fp16
__device__ __half g_wt2[W_ELEMS];
__device__ float g_part[NB_STATS * C * 2];
__device__ float g_scale[C];
__device__ float g_bias[C];

// ---------------- helpers ----------------------------------------------------
__device__ __forceinline__ uint32_t h2_u32(__half2 h) {
    return *reinterpret_cast<uint32_t*>(&h);
}
__device__ __forceinline__ uint32_t smem_u32(const void* p) {
    uint32_t a;
    asm("{ .reg .u64 t; cvta.to.shared.u64 t, %1; cvt.u32.u64 %0, t; }" : "=r"(a) : "l"(p));
    return a;
}
__device__ __forceinline__ void red_add2(float* p, float a, float b) {
    asm volatile("red.global.add.v2.f32 [%0], {%1, %2};"
                 :: "l"(p), "f"(a), "f"(b) : "memory");
}
__device__ __forceinline__ void st2(float* p, float a, float b) {
    asm volatile("st.global.v2.f32 [%0], {%1, %2};"
                 :: "l"(p), "f"(a), "f"(b) : "memory");
}
// L2-only variant for gathered feature rows (no L1 reuse)
__device__ __forceinline__ void cp_async16_cg(uint32_t dst, const void* src, int src_bytes) {
    asm volatile("cp.async.cg.shared.global [%0], [%1], 16, %2;"
                 :: "r"(dst), "l"(src), "r"(src_bytes) : "memory");
}
// L1-caching variant for weights (reused across CTAs of the same offset)
__device__ __forceinline__ void cp_async16_ca(uint32_t dst, const void* src) {
    asm volatile("cp.async.ca.shared.global [%0], [%1], 16;"
                 :: "r"(dst), "l"(src) : "memory");
}
#define CP_COMMIT() asm volatile("cp.async.commit_group;" ::: "memory")
#define CP_WAIT(n)  asm volatile("cp.async.wait_group %0;" :: "n"(n) : "memory")

__device__ __forceinline__ void mma_f16(float* d, const uint32_t* a, const uint32_t* b) {
    asm volatile(
        "mma.sync.aligned.m16n8k16.row.col.f32.f16.f16.f32 "
        "{%0,%1,%2,%3}, {%4,%5,%6,%7}, {%8,%9}, {%0,%1,%2,%3};"
        : "+f"(d[0]), "+f"(d[1]), "+f"(d[2]), "+f"(d[3])
        : "r"(a[0]), "r"(a[1]), "r"(a[2]), "r"(a[3]), "r"(b[0]), "r"(b[1]));
}

// ---- prep: transpose W[k][ci][co] -> Wt[k][co][ci], fp16 --------------------
__global__ void __launch_bounds__(256) prep_w_kernel(const float* __restrict__ W,
                                                     __half* __restrict__ Wt) {
    const int k = blockIdx.y;
    const int idx = blockIdx.x * 256 + threadIdx.x;  // over 16384
    const int ci = idx >> 7;
    const int co = idx & 127;
    float v = __ldg(&W[(long)k * 16384 + ci * 128 + co]);  // coalesced read
    Wt[(long)k * 16384 + co * 128 + ci] = __float2half_rn(v);
}

// ---- one-shot fp16 conversion of features -----------------------------------
__global__ void __launch_bounds__(256) round_kernel(const float4* __restrict__ src,
                                                    __half* __restrict__ dst) {
    int i = blockIdx.x * 256 + threadIdx.x;   // over TOTAL8
    if (i >= TOTAL8) return;
    float4 v0 = __ldg(&src[2 * i]);
    float4 v1 = __ldg(&src[2 * i + 1]);
    uint4 o;
    o.x = h2_u32(__floats2half2_rn(v0.x, v0.y));
    o.y = h2_u32(__floats2half2_rn(v0.z, v0.w));
    o.z = h2_u32(__floats2half2_rn(v1.x, v1.y));
    o.w = h2_u32(__floats2half2_rn(v1.z, v1.w));
    *(uint4*)(dst + 8 * (long)i) = o;
}

// ---- fp16 mma.sync conv: B resident in smem, TPB tiles per CTA --------------
// Tile: 128 pairs x 128 outch x K=128 (A staged in 4 chunk buffers per tile).
// ATOMIC=false: center offset (k=13), plain stores (no zero pass needed).
// ATOMIC=true : 26 remaining offsets, red.global scatter-add.
template <bool ATOMIC>
__global__ void __launch_bounds__(256, 2) conv_mma_kernel(
    const __half* __restrict__ feats, const __half* __restrict__ Wt,
    const int* __restrict__ in_idx, const int* __restrict__ out_idx,
    float* __restrict__ out)
{
    extern __shared__ uint32_t dsm[];      // [B resident][A chunk buffers x4]
    __shared__ int s_ii[TILE_M];
    __shared__ int s_oi[TILE_M];

    const int k = ATOMIC ? (blockIdx.y + (blockIdx.y >= 13 ? 1 : 0)) : 13;
    const int* ik = in_idx + (long)k * N_SITES;
    const long chunk0 = (long)blockIdx.x * TPB;
    // valid pairs form a prefix: if the group's first tile is empty, all are.
    if (ATOMIC && __ldg(&ik[chunk0 * TILE_M]) >= N_SITES) return;
    const int* ok = out_idx + (long)k * N_SITES;

    const int tid = threadIdx.x;
    const int wid = tid >> 5;
    const int lane = tid & 31;
    const int g = lane >> 2;       // group id (row within frag)
    const int tig = lane & 3;      // thread in group

    const int warp_m = wid & 3;    // 0..3 -> 32-row band
    const int warp_n = wid >> 2;   // 0..1 -> 64-col band
    const int m0 = warp_m * 32;
    const int n0 = warp_n * 64;

    const char* fh = (const char*)feats;                 // row = 256 B
    const char* wh = (const char*)(Wt + (long)k * 16384);
    const uint32_t dsm_base = smem_u32(dsm);
    const uint32_t a_base = dsm_base + B_WORDS * 4;

    // ---- load resident B ONCE: warp reads 2 rows x 256 B contiguous ---------
    #pragma unroll
    for (int it = 0; it < 8; it++) {
        int idx = tid + it * 256;          // 2048 granules of 16 B
        int r = idx >> 4, g4 = idx & 15;
        cp_async16_ca(dsm_base + (r * B_ROW_WORDS + g4 * 4) * 4,
                      wh + r * 256 + g4 * 16);
    }
    CP_COMMIT();

    // ---- stage A chunk kc: warp reads 8 rows x 64 B contiguous --------------
    auto stageA = [&](int kc, int pb) {
        const uint32_t a_u32 = a_base + pb * (A_CHUNK_WORDS * 4);
        #pragma unroll
        for (int it = 0; it < 2; it++) {
            int idx = tid + it * 256;      // 512 granules of 16 B
            int r = idx >> 2, g4 = idx & 3;
            int ii = s_ii[r];
            bool v = (ii < N_SITES);
            const char* src = fh + (long)(v ? ii : 0) * 256 + kc * 64 + g4 * 16;
            cp_async16_cg(a_u32 + (r * A_ROW_WORDS + g4 * 4) * 4, src, v ? 16 : 0);
        }
    };

    // ---- compute chunk kc on A buffer pb ------------------------------------
    auto compute = [&](int kc, int pb, float acc[2][8][4]) {
        const uint32_t* Asb = dsm + B_WORDS + pb * A_CHUNK_WORDS;
        #pragma unroll
        for (int ks2 = 0; ks2 < 2; ks2++) {
            const int kwB = kc * 16 + ks2 * 8;   // word offset in 68-word B row
            const int kwA = ks2 * 8;             // word offset in 20-word A row
            uint32_t b[8][2];
            #pragma unroll
            for (int nf = 0; nf < 8; nf++) {
                const int n = n0 + nf * 8 + g;
                b[nf][0] = dsm[n * B_ROW_WORDS + kwB + tig];
                b[nf][1] = dsm[n * B_ROW_WORDS + kwB + tig + 4];
            }
            #pragma unroll
            for (int mf = 0; mf < 2; mf++) {
                const int row = m0 + mf * 16 + g;
                uint32_t a[4];
                a[0] = Asb[row * A_ROW_WORDS + kwA + tig];
                a[1] = Asb[(row + 8) * A_ROW_WORDS + kwA + tig];
                a[2] = Asb[row * A_ROW_WORDS + kwA + tig + 4];
                a[3] = Asb[(row + 8) * A_ROW_WORDS + kwA + tig + 4];
                #pragma unroll
                for (int nf = 0; nf < 8; nf++)
                    mma_f16(acc[mf][nf], a, b[nf]);
            }
        }
    };

    // ---- process TPB tiles with resident B ----------------------------------
    #pragma unroll 1
    for (int t = 0; t < TPB; t++) {
        const long chunk = chunk0 + t;
        if (chunk >= NCHUNK) break;
        const long base = chunk * TILE_M;
        if (ATOMIC && t > 0 && __ldg(&ik[base]) >= N_SITES) break;  // prefix end

        __syncthreads();   // prior tile's compute/epilogue fully retired
        if (tid < TILE_M) {
            long p = base + tid;
            bool v = (p < N_SITES);
            s_ii[tid] = v ? __ldg(&ik[p]) : N_SITES;
            s_oi[tid] = v ? __ldg(&ok[p]) : N_SITES;
        }
        __syncthreads();

        float acc[2][8][4];
        #pragma unroll
        for (int mf = 0; mf < 2; mf++)
            #pragma unroll
            for (int nf = 0; nf < 8; nf++)
                #pragma unroll
                for (int r = 0; r < 4; r++) acc[mf][nf][r] = 0.f;

        stageA(0, 0); CP_COMMIT();
        stageA(1, 1); CP_COMMIT();
        stageA(2, 2); CP_COMMIT();
        stageA(3, 3); CP_COMMIT();
        // tile 0: WAIT(3) also covers the B group (4 newer A groups pending-3)
        CP_WAIT(3); __syncthreads(); compute(0, 0, acc);
        CP_WAIT(2); __syncthreads(); compute(1, 1, acc);
        CP_WAIT(1); __syncthreads(); compute(2, 2, acc);
        CP_WAIT(0); __syncthreads(); compute(3, 3, acc);

        // ---- epilogue: rows -> out[oi] --------------------------------------
        #pragma unroll
        for (int mf = 0; mf < 2; mf++) {
            const int r_lo = m0 + mf * 16 + g;
            const int oi_lo = s_oi[r_lo];
            const int oi_hi = s_oi[r_lo + 8];
            #pragma unroll
            for (int nf = 0; nf < 8; nf++) {
                const int col = n0 + nf * 8 + 2 * tig;
                if (oi_lo < N_SITES) {
                    float* p = out + (long)oi_lo * C + col;
                    if (ATOMIC) red_add2(p, acc[mf][nf][0], acc[mf][nf][1]);
                    else        st2(p, acc[mf][nf][0], acc[mf][nf][1]);
                }
                if (oi_hi < N_SITES) {
                    float* p = out + (long)oi_hi * C + col;
                    if (ATOMIC) red_add2(p, acc[mf][nf][2], acc[mf][nf][3]);
                    else        st2(p, acc[mf][nf][2], acc[mf][nf][3]);
                }
            }
        }
    }
}

// ---------------- BN stats: per-block partial sum / sumsq per channel -------
__global__ void __launch_bounds__(256) bn_stats_kernel(const float* __restrict__ x) {
    const int b = blockIdx.x;
    const int r0 = b * STATS_ROWS;
    const int r1 = min(r0 + STATS_ROWS, N_SITES);
    const int c = threadIdx.x & 127;
    const int half = threadIdx.x >> 7;

    float s = 0.f, ss = 0.f;
    for (int r = r0 + half; r < r1; r += 2) {
        float v = __ldg(&x[(long)r * C + c]);
        s += v;
        ss += v * v;
    }
    __shared__ float sm[512];
    sm[threadIdx.x] = s;
    sm[256 + threadIdx.x] = ss;
    __syncthreads();
    if (half == 0) {
        g_part[((long)b * C + c) * 2 + 0] = s + sm[threadIdx.x + 128];
        g_part[((long)b * C + c) * 2 + 1] = ss + sm[256 + threadIdx.x + 128];
    }
}

// fixed-order finalize (4 workers per channel): deterministic mean/var
__global__ void __launch_bounds__(512) bn_final_kernel(const float* __restrict__ gamma,
                                                       const float* __restrict__ beta) {
    const int c = threadIdx.x & 127;
    const int w = threadIdx.x >> 7;  // 0..3
    float s = 0.f, ss = 0.f;
    for (int b = w; b < NB_STATS; b += 4) {
        s  += g_part[((long)b * C + c) * 2 + 0];
        ss += g_part[((long)b * C + c) * 2 + 1];
    }
    __shared__ float sm[1024];
    sm[threadIdx.x] = s;
    sm[512 + threadIdx.x] = ss;
    __syncthreads();
    if (w == 0) {
        #pragma unroll
        for (int j = 1; j < 4; j++) {
            s  += sm[j * 128 + c];
            ss += sm[512 + j * 128 + c];
        }
        const float inv_n = 1.f / (float)N_SITES;
        float m = s * inv_n;
        float v = ss * inv_n - m * m;
        float sc = gamma[c] * rsqrtf(v + EPS);
        g_scale[c] = sc;
        g_bias[c] = beta[c] - m * sc;
    }
}

// ---- elementwise: BN + ReLU, emit fp16 only (conv2 input) -------------------
__global__ void __launch_bounds__(256) bn_relu_kernel(const float* __restrict__ x,
                                                      __half* __restrict__ dst) {
    int i = blockIdx.x * 256 + threadIdx.x;   // over TOTAL4
    if (i >= TOTAL4) return;
    float4 v = ((const float4*)x)[i];
    int c4 = i & 31;
    float4 s = ((const float4*)g_scale)[c4];
    float4 b = ((const float4*)g_bias)[c4];
    float ox = fmaxf(fmaf(v.x, s.x, b.x), 0.f);
    float oy = fmaxf(fmaf(v.y, s.y, b.y), 0.f);
    float oz = fmaxf(fmaf(v.z, s.z, b.z), 0.f);
    float ow = fmaxf(fmaf(v.w, s.w, b.w), 0.f);
    uint2 o;
    o.x = h2_u32(__floats2half2_rn(ox, oy));
    o.y = h2_u32(__floats2half2_rn(oz, ow));
    *(uint2*)(dst + 4 * (long)i) = o;
}

// ---------------- elementwise: BN + residual + ReLU -> output ---------------
__global__ void __launch_bounds__(256) apply_res_kernel(
    const float* __restrict__ x, const float* __restrict__ feats,
    float* __restrict__ out)
{
    int i = blockIdx.x * 256 + threadIdx.x;
    if (i >= TOTAL4) return;
    float4 v = ((const float4*)x)[i];
    float4 f = ((const float4*)feats)[i];
    int c4 = i & 31;
    float4 s = ((const float4*)g_scale)[c4];
    float4 b = ((const float4*)g_bias)[c4];
    float4 o;
    o.x = fmaxf(fmaf(v.x, s.x, b.x) + f.x, 0.f);
    o.y = fmaxf(fmaf(v.y, s.y, b.y) + f.y, 0.f);
    o.z = fmaxf(fmaf(v.z, s.z, b.z) + f.z, 0.f);
    o.w = fmaxf(fmaf(v.w, s.w, b.w) + f.w, 0.f);
    ((float4*)out)[i] = o;
}

// ---------------- launch ----------------------------------------------------
extern "C" void kernel_launch(void* const* d_in, const int* in_sizes, int n_in,
                              void* d_out, int out_size) {
    const float* feats  = (const float*)d_in[0];
    const float* W1     = (const float*)d_in[1];
    const float* gamma1 = (const float*)d_in[2];
    const float* beta1  = (const float*)d_in[3];
    const float* W2     = (const float*)d_in[4];
    const float* gamma2 = (const float*)d_in[5];
    const float* beta2  = (const float*)d_in[6];
    const int*   iidx   = (const int*)d_in[7];
    const int*   oidx   = (const int*)d_in[8];
    float* out = (float*)d_out;

    void *pb1, *pb2, *ph, *pw1, *pw2;
    cudaGetSymbolAddress(&pb1, g_buf1);
    cudaGetSymbolAddress(&pb2, g_buf2);
    cudaGetSymbolAddress(&ph,  g_h);
    cudaGetSymbolAddress(&pw1, g_wt1);
    cudaGetSymbolAddress(&pw2, g_wt2);
    float*  buf1 = (float*)pb1;
    float*  buf2 = (float*)pb2;
    __half* fh   = (__half*)ph;
    __half* wt1  = (__half*)pw1;
    __half* wt2  = (__half*)pw2;

    cudaFuncSetAttribute(conv_mma_kernel<false>,
                         cudaFuncAttributeMaxDynamicSharedMemorySize, SMEM_DYN_BYTES);
    cudaFuncSetAttribute(conv_mma_kernel<true>,
                         cudaFuncAttributeMaxDynamicSharedMemorySize, SMEM_DYN_BYTES);

    const int EB4 = (TOTAL4 + 255) / 256;
    const int EB8 = (TOTAL8 + 255) / 256;
    dim3 cgc(NGROUP, 1);    // center store pass  (4 tiles per CTA)
    dim3 cga(NGROUP, 26);   // atomic pass (26 non-center offsets)
    dim3 pg(64, NOFF);

    // weight transpose -> fp16; fp16 copy of features
    prep_w_kernel<<<pg, 256>>>(W1, wt1);
    prep_w_kernel<<<pg, 256>>>(W2, wt2);
    round_kernel<<<EB8, 256>>>((const float4*)feats, fh);

    // conv1 (center store, then 26-offset scatter) -> BN1 -> ReLU -> fp16
    conv_mma_kernel<false><<<cgc, 256, SMEM_DYN_BYTES>>>(fh, wt1, iidx, oidx, buf1);
    conv_mma_kernel<true ><<<cga, 256, SMEM_DYN_BYTES>>>(fh, wt1, iidx, oidx, buf1);
    bn_stats_kernel<<<NB_STATS, 256>>>(buf1);
    bn_final_kernel<<<1, 512>>>(gamma1, beta1);
    bn_relu_kernel<<<EB4, 256>>>(buf1, fh);

    // conv2 -> BN2 -> +residual -> ReLU
    conv_mma_kernel<false><<<cgc, 256, SMEM_DYN_BYTES>>>(fh, wt2, iidx, oidx, buf2);
    conv_mma_kernel<true ><<<cga, 256, SMEM_DYN_BYTES>>>(fh, wt2, iidx, oidx, buf2);
    bn_stats_kernel<<<NB_STATS, 256>>>(buf2);
    bn_final_kernel<<<1, 512>>>(gamma2, beta2);
    apply_res_kernel<<<EB4, 256>>>(buf2, feats, out);
}